// round 7
// baseline (speedup 1.0000x reference)
#include <cuda_runtime.h>

#define B_TOTAL 1048576
#define NU 6041
#define NM 3953
#define EMB 32
#define NG 18
#define D_IN 85
#define H1 64
#define H2 32
#define H3 16
#define THREADS 256
#define BLOCKS 1024

typedef unsigned long long u64;

__device__ __forceinline__ u64 pack1(float v) {
    u64 r; asm("mov.b64 %0, {%1,%1};" : "=l"(r) : "f"(v)); return r;
}
__device__ __forceinline__ void unpack2(u64 v, float& lo, float& hi) {
    asm("mov.b64 {%0,%1}, %2;" : "=f"(lo), "=f"(hi) : "l"(v));
}
__device__ __forceinline__ u64 ffma2(u64 a, u64 b, u64 c) {
    u64 d; asm("fma.rn.f32x2 %0, %1, %2, %3;" : "=l"(d) : "l"(a), "l"(b), "l"(c)); return d;
}

__global__ __launch_bounds__(THREADS, 2)
void wd_kernel(const int* __restrict__ uids, const int* __restrict__ mids,
               const float* __restrict__ gender, const float* __restrict__ age,
               const float* __restrict__ occ, const float* __restrict__ genres,
               const float* __restrict__ wideW, const float* __restrict__ wideB,
               const float* __restrict__ utab, const float* __restrict__ mtab,
               const float* __restrict__ W1, const float* __restrict__ b1,
               const float* __restrict__ W2, const float* __restrict__ b2,
               const float* __restrict__ W3, const float* __restrict__ b3,
               const float* __restrict__ W4, const float* __restrict__ b4,
               float* __restrict__ out)
{
    __shared__ __align__(16) float sW1[D_IN * H1];   // 21760 B
    __shared__ __align__(16) float sW2[H1 * H2];     //  8192 B
    __shared__ __align__(16) float sW3[H2 * H3];     //  2048 B
    __shared__ __align__(16) float sW4[H3];
    __shared__ __align__(16) float sB1[H1];
    __shared__ __align__(16) float sB2[H2];
    __shared__ __align__(16) float sB3[H3];
    __shared__ float sWr[24];
    __shared__ float sScal[2];   // [0]=b4, [1]=wide_b

    const int tid = threadIdx.x;
    for (int i = tid; i < D_IN * H1; i += THREADS) sW1[i] = W1[i];
    for (int i = tid; i < H1 * H2;  i += THREADS) sW2[i] = W2[i];
    for (int i = tid; i < H2 * H3;  i += THREADS) sW3[i] = W3[i];
    if (tid < H3) sW4[tid] = W4[tid];
    if (tid < H1) sB1[tid] = b1[tid];
    if (tid < H2) sB2[tid] = b2[tid];
    if (tid < H3) sB3[tid] = b3[tid];
    if (tid < 21) sWr[tid] = wideW[NU + NM + tid];
    if (tid == 0) { sScal[0] = b4[0]; sScal[1] = wideB[0]; }
    __syncthreads();

    for (int r = blockIdx.x * THREADS + tid; r < B_TOTAL; r += gridDim.x * THREADS) {
        const int uid = uids[r];
        const int mid = mids[r];
        float wide = sScal[1] + wideW[uid] + wideW[NU + mid];

        // ---- layer 1: 85 -> 64, accumulators as 32 packed f32x2 ----
        u64 acc[H1 / 2];
        {
            const ulonglong2* pb = (const ulonglong2*)sB1;
            #pragma unroll
            for (int j = 0; j < H1 / 4; j++) {
                ulonglong2 t = pb[j];
                acc[2 * j] = t.x; acc[2 * j + 1] = t.y;
            }
        }

        auto step1 = [&](int k, float x) {
            u64 xx = pack1(x);
            const ulonglong2* w = (const ulonglong2*)(sW1 + k * H1);
            #pragma unroll
            for (int j = 0; j < H1 / 4; j++) {
                ulonglong2 t = w[j];
                acc[2 * j]     = ffma2(xx, t.x, acc[2 * j]);
                acc[2 * j + 1] = ffma2(xx, t.y, acc[2 * j + 1]);
            }
        };

        const float4* up = (const float4*)(utab + uid * EMB);
        #pragma unroll 2
        for (int c = 0; c < 8; c++) {
            float4 x = up[c];
            step1(4 * c + 0, x.x); step1(4 * c + 1, x.y);
            step1(4 * c + 2, x.z); step1(4 * c + 3, x.w);
        }
        const float4* mp = (const float4*)(mtab + mid * EMB);
        #pragma unroll 2
        for (int c = 0; c < 8; c++) {
            float4 x = mp[c];
            step1(32 + 4 * c, x.x); step1(33 + 4 * c, x.y);
            step1(34 + 4 * c, x.z); step1(35 + 4 * c, x.w);
        }
        {
            float g = gender[r]; wide += g * sWr[0]; step1(64, g);
            float a = age[r];    wide += a * sWr[1]; step1(65, a);
            float o = occ[r];    wide += o * sWr[2]; step1(66, o);
        }
        const float* gp = genres + (long long)r * NG;
        #pragma unroll 3
        for (int q = 0; q < NG; q++) {
            float v = gp[q];
            wide += v * sWr[3 + q];
            step1(67 + q, v);
        }

        float h[H1];
        #pragma unroll
        for (int j = 0; j < H1 / 2; j++) {
            float lo, hi; unpack2(acc[j], lo, hi);
            h[2 * j]     = fmaxf(lo, 0.0f);
            h[2 * j + 1] = fmaxf(hi, 0.0f);
        }

        // ---- layer 2: 64 -> 32 ----
        u64 acc2[H2 / 2];
        {
            const ulonglong2* pb = (const ulonglong2*)sB2;
            #pragma unroll
            for (int j = 0; j < H2 / 4; j++) {
                ulonglong2 t = pb[j];
                acc2[2 * j] = t.x; acc2[2 * j + 1] = t.y;
            }
        }
        #pragma unroll
        for (int k = 0; k < H1; k++) {
            u64 xx = pack1(h[k]);
            const ulonglong2* w = (const ulonglong2*)(sW2 + k * H2);
            #pragma unroll
            for (int j = 0; j < H2 / 4; j++) {
                ulonglong2 t = w[j];
                acc2[2 * j]     = ffma2(xx, t.x, acc2[2 * j]);
                acc2[2 * j + 1] = ffma2(xx, t.y, acc2[2 * j + 1]);
            }
        }
        float h2[H2];
        #pragma unroll
        for (int j = 0; j < H2 / 2; j++) {
            float lo, hi; unpack2(acc2[j], lo, hi);
            h2[2 * j]     = fmaxf(lo, 0.0f);
            h2[2 * j + 1] = fmaxf(hi, 0.0f);
        }

        // ---- layer 3: 32 -> 16 ----
        u64 acc3[H3 / 2];
        {
            const ulonglong2* pb = (const ulonglong2*)sB3;
            #pragma unroll
            for (int j = 0; j < H3 / 4; j++) {
                ulonglong2 t = pb[j];
                acc3[2 * j] = t.x; acc3[2 * j + 1] = t.y;
            }
        }
        #pragma unroll
        for (int k = 0; k < H2; k++) {
            u64 xx = pack1(h2[k]);
            const ulonglong2* w = (const ulonglong2*)(sW3 + k * H3);
            #pragma unroll
            for (int j = 0; j < H3 / 4; j++) {
                ulonglong2 t = w[j];
                acc3[2 * j]     = ffma2(xx, t.x, acc3[2 * j]);
                acc3[2 * j + 1] = ffma2(xx, t.y, acc3[2 * j + 1]);
            }
        }

        // ---- layer 4: 16 -> 1, + wide, sigmoid ----
        float d = sScal[0];
        #pragma unroll
        for (int j = 0; j < H3 / 2; j++) {
            float lo, hi; unpack2(acc3[j], lo, hi);
            d = fmaf(fmaxf(lo, 0.0f), sW4[2 * j],     d);
            d = fmaf(fmaxf(hi, 0.0f), sW4[2 * j + 1], d);
        }
        float z = wide + d;
        out[r] = 1.0f / (1.0f + expf(-z));
    }
}

extern "C" void kernel_launch(void* const* d_in, const int* in_sizes, int n_in,
                              void* d_out, int out_size) {
    const int*   uids   = (const int*)  d_in[0];
    const int*   mids   = (const int*)  d_in[1];
    const float* gender = (const float*)d_in[2];
    const float* age    = (const float*)d_in[3];
    const float* occ    = (const float*)d_in[4];
    const float* genres = (const float*)d_in[5];
    const float* wideW  = (const float*)d_in[6];
    const float* wideB  = (const float*)d_in[7];
    const float* utab   = (const float*)d_in[8];
    const float* mtab   = (const float*)d_in[9];
    const float* W1     = (const float*)d_in[10];
    const float* b1     = (const float*)d_in[11];
    const float* W2     = (const float*)d_in[12];
    const float* b2     = (const float*)d_in[13];
    const float* W3     = (const float*)d_in[14];
    const float* b3     = (const float*)d_in[15];
    const float* W4     = (const float*)d_in[16];
    const float* b4     = (const float*)d_in[17];
    float* out = (float*)d_out;

    wd_kernel<<<BLOCKS, THREADS>>>(uids, mids, gender, age, occ, genres,
                                   wideW, wideB, utab, mtab,
                                   W1, b1, W2, b2, W3, b3, W4, b4, out);
}

// round 9
// speedup vs baseline: 3.6971x; 3.6971x over previous
#include <cuda_runtime.h>
#include <cuda_bf16.h>
#include <stdint.h>

#define NU 6041
#define NM 3953
#define B_TOTAL 1048576
#define NTILES 8192          // 128 rows per tile
#define GRID 592
#define THREADS 256          // 8 warps, 16 rows/warp

typedef unsigned long long u64;
typedef unsigned int u32;

__device__ uint2 gB1[6 * 8 * 32];   // W1 B-fragments [kt][nt][lane]
__device__ uint2 gB2[4 * 4 * 32];   // W2 B-fragments [kt][nt][lane]

// ---------------- helpers ----------------
__device__ __forceinline__ u32 pkbf(float lo, float hi) {
    u32 r; asm("cvt.rn.bf16x2.f32 %0,%1,%2;" : "=r"(r) : "f"(hi), "f"(lo)); return r;
}
__device__ __forceinline__ u64 pack1(float v) {
    u64 r; asm("mov.b64 %0,{%1,%1};" : "=l"(r) : "f"(v)); return r;
}
__device__ __forceinline__ void unpack2(u64 v, float& lo, float& hi) {
    asm("mov.b64 {%0,%1},%2;" : "=f"(lo), "=f"(hi) : "l"(v));
}
__device__ __forceinline__ u64 ffma2(u64 a, u64 b, u64 c) {
    u64 d; asm("fma.rn.f32x2 %0,%1,%2,%3;" : "=l"(d) : "l"(a), "l"(b), "l"(c)); return d;
}
__device__ __forceinline__ u64 addf2(u64 a, u64 b) {
    u64 d; asm("add.rn.f32x2 %0,%1,%2;" : "=l"(d) : "l"(a), "l"(b)); return d;
}
__device__ __forceinline__ void mma16816(float* c, u32 a0, u32 a1, u32 a2, u32 a3,
                                         u32 b0, u32 b1) {
    asm("mma.sync.aligned.m16n8k16.row.col.f32.bf16.bf16.f32 "
        "{%0,%1,%2,%3},{%4,%5,%6,%7},{%8,%9},{%0,%1,%2,%3};"
        : "+f"(c[0]), "+f"(c[1]), "+f"(c[2]), "+f"(c[3])
        : "r"(a0), "r"(a1), "r"(a2), "r"(a3), "r"(b0), "r"(b1));
}
__device__ __forceinline__ float relu(float x) { return fmaxf(x, 0.f); }

// ---------------- weight fragment prep ----------------
// B-fragment layout (m16n8k16 col-major B): lane = g*4+t (g=lane>>2, t=lane&3)
//   b0 = {B[2t][n=g_base+g], B[2t+1][n]},  b1 = {B[2t+8][n], B[2t+9][n]}
__global__ void prep_kernel(const float* __restrict__ W1, const float* __restrict__ W2) {
    int i = blockIdx.x * blockDim.x + threadIdx.x;
    int stride = gridDim.x * blockDim.x;
    for (int idx = i; idx < 6 * 8 * 32; idx += stride) {
        int lane = idx & 31, nt = (idx >> 5) & 7, kt = idx >> 8;
        int g = lane >> 2, t = lane & 3;
        int n = nt * 8 + g;
        int k0 = kt * 16 + t * 2;
        float v0 = (k0     < 85) ? W1[(k0    ) * 64 + n] : 0.f;
        float v1 = (k0 + 1 < 85) ? W1[(k0 + 1) * 64 + n] : 0.f;
        float v2 = (k0 + 8 < 85) ? W1[(k0 + 8) * 64 + n] : 0.f;
        float v3 = (k0 + 9 < 85) ? W1[(k0 + 9) * 64 + n] : 0.f;
        gB1[idx] = make_uint2(pkbf(v0, v1), pkbf(v2, v3));
    }
    for (int idx = i; idx < 4 * 4 * 32; idx += stride) {
        int lane = idx & 31, nt = (idx >> 5) & 3, kt = idx >> 7;
        int g = lane >> 2, t = lane & 3;
        int n = nt * 8 + g;
        int k0 = kt * 16 + t * 2;
        gB2[idx] = make_uint2(pkbf(W2[k0 * 32 + n],       W2[(k0 + 1) * 32 + n]),
                              pkbf(W2[(k0 + 8) * 32 + n], W2[(k0 + 9) * 32 + n]));
    }
}

// ---------------- main kernel ----------------
#define AW 56   // u32 words per A1 row (112 bf16, padded vs 96 used)

__global__ void __launch_bounds__(THREADS)
wd_mma(const int* __restrict__ uids, const int* __restrict__ mids,
       const float* __restrict__ gender, const float* __restrict__ age,
       const float* __restrict__ occ, const float* __restrict__ genres,
       const float* __restrict__ wideW, const float* __restrict__ wideB,
       const float* __restrict__ utab, const float* __restrict__ mtab,
       const float* __restrict__ W3, const float* __restrict__ b1,
       const float* __restrict__ b2, const float* __restrict__ b3,
       const float* __restrict__ W4, const float* __restrict__ b4,
       float* __restrict__ out)
{
    __shared__ __align__(16) u32   sA1[8][16 * AW];     // 28672 B (per-warp A staging)
    __shared__ __align__(16) uint2 sB1f[6 * 8 * 32];    // 12288 B
    __shared__ __align__(16) uint2 sB2f[4 * 4 * 32];    //  4096 B
    __shared__ __align__(16) float sW3[32 * 20];        //  2560 B (rows padded to 20)
    __shared__ __align__(16) float sB1b[64];
    __shared__ __align__(16) float sB2b[32];
    __shared__ __align__(16) float sB3b[16];
    __shared__ __align__(16) float sW4v[16];
    __shared__ __align__(16) float sWr[24];
    __shared__ float sSc[2];
    __shared__ float sWide[8 * 16];

    const int tid  = threadIdx.x;
    const int wid  = tid >> 5;
    const int lane = tid & 31;
    const int g    = lane >> 2;
    const int t4   = lane & 3;

    // ---- one-time staging ----
    for (int i = tid; i < 6 * 8 * 32; i += THREADS) sB1f[i] = gB1[i];
    for (int i = tid; i < 4 * 4 * 32; i += THREADS) sB2f[i] = gB2[i];
    for (int i = tid; i < 512; i += THREADS) sW3[(i >> 4) * 20 + (i & 15)] = W3[i];
    if (tid < 64) sB1b[tid] = b1[tid];
    if (tid < 32) sB2b[tid] = b2[tid];
    if (tid < 16) sB3b[tid] = b3[tid];
    if (tid < 16) sW4v[tid] = W4[tid];
    if (tid < 21) sWr[tid]  = wideW[NU + NM + tid];
    if (tid == 0) { sSc[0] = b4[0]; sSc[1] = wideB[0]; }
    __syncthreads();

    for (int tile = blockIdx.x; tile < NTILES; tile += gridDim.x) {
        const int R = tile * 128 + wid * 16;
        __syncwarp();   // previous iteration's A reads done before new stores

        // ---- gather embeddings: 2 lanes per row, bf16-pack into A1 cols 0..63 ----
        {
            const int row  = lane >> 1;
            const int half = lane & 1;
            const int rl = R + row;
            const int uidh = uids[rl];
            const int midh = mids[rl];
            u32* rb = &sA1[wid][row * AW];
            const float4* up = (const float4*)(utab + (size_t)uidh * 32) + half * 4;
            float4 x0 = up[0], x1 = up[1], x2 = up[2], x3 = up[3];
            uint4 v;
            v.x = pkbf(x0.x, x0.y); v.y = pkbf(x0.z, x0.w);
            v.z = pkbf(x1.x, x1.y); v.w = pkbf(x1.z, x1.w);
            *(uint4*)(rb + half * 8) = v;
            v.x = pkbf(x2.x, x2.y); v.y = pkbf(x2.z, x2.w);
            v.z = pkbf(x3.x, x3.y); v.w = pkbf(x3.z, x3.w);
            *(uint4*)(rb + half * 8 + 4) = v;
            const float4* mp = (const float4*)(mtab + (size_t)midh * 32) + half * 4;
            x0 = mp[0]; x1 = mp[1]; x2 = mp[2]; x3 = mp[3];
            v.x = pkbf(x0.x, x0.y); v.y = pkbf(x0.z, x0.w);
            v.z = pkbf(x1.x, x1.y); v.w = pkbf(x1.z, x1.w);
            *(uint4*)(rb + 16 + half * 8) = v;
            v.x = pkbf(x2.x, x2.y); v.y = pkbf(x2.z, x2.w);
            v.z = pkbf(x3.x, x3.y); v.w = pkbf(x3.z, x3.w);
            *(uint4*)(rb + 16 + half * 8 + 4) = v;
        }

        // ---- rest features + wide path (lanes 0..15, one row each) ----
        if (lane < 16) {
            const int r = R + lane;
            float fv[21];
            fv[0] = gender[r]; fv[1] = age[r]; fv[2] = occ[r];
            const float2* gp = (const float2*)(genres + (size_t)r * 18);
            #pragma unroll
            for (int q = 0; q < 9; q++) { float2 p = gp[q]; fv[3 + 2*q] = p.x; fv[4 + 2*q] = p.y; }
            float wide = sSc[1] + wideW[uids[r]] + wideW[NU + mids[r]];
            #pragma unroll
            for (int i = 0; i < 21; i++) wide = fmaf(fv[i], sWr[i], wide);
            sWide[wid * 16 + lane] = wide;

            u32 w[16];
            #pragma unroll
            for (int j = 0; j < 10; j++) w[j] = pkbf(fv[2*j], fv[2*j + 1]);
            w[10] = pkbf(fv[20], 0.f);
            w[11] = w[12] = w[13] = w[14] = w[15] = 0u;
            u32* rb = &sA1[wid][lane * AW + 32];
            #pragma unroll
            for (int j = 0; j < 4; j++)
                *(uint4*)(rb + j * 4) = make_uint4(w[4*j], w[4*j+1], w[4*j+2], w[4*j+3]);
        }
        __syncwarp();

        // ---- layer 1: [16x64] = A1[16x96] * W1 ----
        float acc[8][4];
        #pragma unroll
        for (int nt = 0; nt < 8; nt++)
            acc[nt][0] = acc[nt][1] = acc[nt][2] = acc[nt][3] = 0.f;
        const u32* ab = &sA1[wid][0];
        #pragma unroll
        for (int kt = 0; kt < 6; kt++) {
            u32 a0 = ab[g * AW + kt * 8 + t4];
            u32 a1 = ab[(g + 8) * AW + kt * 8 + t4];
            u32 a2 = ab[g * AW + kt * 8 + t4 + 4];
            u32 a3 = ab[(g + 8) * AW + kt * 8 + t4 + 4];
            #pragma unroll
            for (int nt = 0; nt < 8; nt++) {
                uint2 b = sB1f[(kt * 8 + nt) * 32 + lane];
                mma16816(acc[nt], a0, a1, a2, a3, b.x, b.y);
            }
        }

        // ---- epilogue 1: bias+relu, C-frag -> A-frag (registers only) ----
        u32 a2f[4][4];
        #pragma unroll
        for (int kt = 0; kt < 4; kt++) {
            int j0 = 2 * kt, j1 = j0 + 1;
            float2 bb0 = *(const float2*)(sB1b + j0 * 8 + t4 * 2);
            float2 bb1 = *(const float2*)(sB1b + j1 * 8 + t4 * 2);
            a2f[kt][0] = pkbf(relu(acc[j0][0] + bb0.x), relu(acc[j0][1] + bb0.y));
            a2f[kt][1] = pkbf(relu(acc[j0][2] + bb0.x), relu(acc[j0][3] + bb0.y));
            a2f[kt][2] = pkbf(relu(acc[j1][0] + bb1.x), relu(acc[j1][1] + bb1.y));
            a2f[kt][3] = pkbf(relu(acc[j1][2] + bb1.x), relu(acc[j1][3] + bb1.y));
        }

        // ---- layer 2: [16x32] = H1[16x64] * W2 ----
        float acc2[4][4];
        #pragma unroll
        for (int nt = 0; nt < 4; nt++)
            acc2[nt][0] = acc2[nt][1] = acc2[nt][2] = acc2[nt][3] = 0.f;
        #pragma unroll
        for (int kt = 0; kt < 4; kt++)
            #pragma unroll
            for (int nt = 0; nt < 4; nt++) {
                uint2 b = sB2f[(kt * 4 + nt) * 32 + lane];
                mma16816(acc2[nt], a2f[kt][0], a2f[kt][1], a2f[kt][2], a2f[kt][3], b.x, b.y);
            }

        // ---- layer 3 partials (f32x2), rows g and g+8 ----
        u64 pg[8], ph[8];
        #pragma unroll
        for (int m = 0; m < 8; m++) { pg[m] = 0ULL; ph[m] = 0ULL; }
        #pragma unroll
        for (int nt = 0; nt < 4; nt++) {
            float2 bb = *(const float2*)(sB2b + nt * 8 + t4 * 2);
            float hg0 = relu(acc2[nt][0] + bb.x), hg1 = relu(acc2[nt][1] + bb.y);
            float hh0 = relu(acc2[nt][2] + bb.x), hh1 = relu(acc2[nt][3] + bb.y);
            int k0 = nt * 8 + t4 * 2;
            const ulonglong2* w0 = (const ulonglong2*)(sW3 + k0 * 20);
            const ulonglong2* w1 = (const ulonglong2*)(sW3 + (k0 + 1) * 20);
            u64 xg0 = pack1(hg0), xg1 = pack1(hg1);
            u64 xh0 = pack1(hh0), xh1 = pack1(hh1);
            #pragma unroll
            for (int m = 0; m < 4; m++) {
                ulonglong2 t0 = w0[m], t1 = w1[m];
                pg[2*m]   = ffma2(xg0, t0.x, pg[2*m]);
                pg[2*m+1] = ffma2(xg0, t0.y, pg[2*m+1]);
                pg[2*m]   = ffma2(xg1, t1.x, pg[2*m]);
                pg[2*m+1] = ffma2(xg1, t1.y, pg[2*m+1]);
                ph[2*m]   = ffma2(xh0, t0.x, ph[2*m]);
                ph[2*m+1] = ffma2(xh0, t0.y, ph[2*m+1]);
                ph[2*m]   = ffma2(xh1, t1.x, ph[2*m]);
                ph[2*m+1] = ffma2(xh1, t1.y, ph[2*m+1]);
            }
        }
        // reduce partials across the quad
        #pragma unroll
        for (int m = 0; m < 8; m++) {
            pg[m] = addf2(pg[m], __shfl_xor_sync(0xffffffffu, pg[m], 1));
            pg[m] = addf2(pg[m], __shfl_xor_sync(0xffffffffu, pg[m], 2));
            ph[m] = addf2(ph[m], __shfl_xor_sync(0xffffffffu, ph[m], 1));
            ph[m] = addf2(ph[m], __shfl_xor_sync(0xffffffffu, ph[m], 2));
        }

        // ---- layer 4 + sigmoid (one lane per row-pair) ----
        if (t4 == 0) {
            float dpg = sSc[0], dph = sSc[0];
            #pragma unroll
            for (int m = 0; m < 8; m++) {
                float lo, hi;
                unpack2(pg[m], lo, hi);
                dpg = fmaf(relu(lo + sB3b[2*m]),     sW4v[2*m],     dpg);
                dpg = fmaf(relu(hi + sB3b[2*m + 1]), sW4v[2*m + 1], dpg);
                unpack2(ph[m], lo, hi);
                dph = fmaf(relu(lo + sB3b[2*m]),     sW4v[2*m],     dph);
                dph = fmaf(relu(hi + sB3b[2*m + 1]), sW4v[2*m + 1], dph);
            }
            float zg = sWide[wid * 16 + g]     + dpg;
            float zh = sWide[wid * 16 + g + 8] + dph;
            out[R + g]     = 1.f / (1.f + expf(-zg));
            out[R + g + 8] = 1.f / (1.f + expf(-zh));
        }
    }
}

extern "C" void kernel_launch(void* const* d_in, const int* in_sizes, int n_in,
                              void* d_out, int out_size) {
    const int*   uids   = (const int*)  d_in[0];
    const int*   mids   = (const int*)  d_in[1];
    const float* gender = (const float*)d_in[2];
    const float* age    = (const float*)d_in[3];
    const float* occ    = (const float*)d_in[4];
    const float* genres = (const float*)d_in[5];
    const float* wideW  = (const float*)d_in[6];
    const float* wideB  = (const float*)d_in[7];
    const float* utab   = (const float*)d_in[8];
    const float* mtab   = (const float*)d_in[9];
    const float* W1     = (const float*)d_in[10];
    const float* b1     = (const float*)d_in[11];
    const float* W2     = (const float*)d_in[12];
    const float* b2     = (const float*)d_in[13];
    const float* W3     = (const float*)d_in[14];
    const float* b3     = (const float*)d_in[15];
    const float* W4     = (const float*)d_in[16];
    const float* b4     = (const float*)d_in[17];
    float* out = (float*)d_out;

    prep_kernel<<<4, 256>>>(W1, W2);
    wd_mma<<<GRID, THREADS>>>(uids, mids, gender, age, occ, genres,
                              wideW, wideB, utab, mtab,
                              W3, b1, b2, b3, W4, b4, out);
}

// round 10
// speedup vs baseline: 6.1732x; 1.6697x over previous
#include <cuda_runtime.h>
#include <cuda_bf16.h>
#include <stdint.h>

#define NU 6041
#define NM 3953
#define B_TOTAL 1048576
#define NTILES 8192          // 128 rows per CTA-tile
#define GRID 444
#define THREADS 256          // 8 warps, 16 rows/warp
#define AW 52                // u32 words per A1 row (stride chosen so 20*g mod 32 covers all 8 slots)

typedef unsigned long long u64;
typedef unsigned int u32;

// ---- dynamic smem offsets (bytes) ----
#define OFF_A1    0u        // 8 warps * 16 rows * 52 words * 4 = 26624
#define OFF_B1F   26624u    // 12288
#define OFF_B2F   38912u    // 4096
#define OFF_G     43008u    // 8 * 288 * 4 = 9216
#define OFF_IDS   52224u    // 8 * 32 * 4 = 1024
#define OFF_WIDE  53248u    // 512
#define OFF_B1B   53760u    // 256
#define OFF_B2B   54016u    // 128
#define OFF_WR    54144u    // 96
#define OFF_SC    54240u    // 16
#define SMEM_BYTES 54272

__device__ uint2 gB1[6 * 8 * 32];   // W1 B-fragments [kt][nt][lane]
__device__ uint2 gB2[4 * 4 * 32];   // W2 B-fragments [kt][nt][lane]
__device__ uint2 gB3[2 * 2 * 32];   // W3 B-fragments [kt][nt][lane]

// ---------------- helpers ----------------
__device__ __forceinline__ u32 pkbf(float lo, float hi) {
    u32 r; asm("cvt.rn.bf16x2.f32 %0,%1,%2;" : "=r"(r) : "f"(hi), "f"(lo)); return r;
}
__device__ __forceinline__ void mma16816(float* c, u32 a0, u32 a1, u32 a2, u32 a3,
                                         u32 b0, u32 b1) {
    asm("mma.sync.aligned.m16n8k16.row.col.f32.bf16.bf16.f32 "
        "{%0,%1,%2,%3},{%4,%5,%6,%7},{%8,%9},{%0,%1,%2,%3};"
        : "+f"(c[0]), "+f"(c[1]), "+f"(c[2]), "+f"(c[3])
        : "r"(a0), "r"(a1), "r"(a2), "r"(a3), "r"(b0), "r"(b1));
}
__device__ __forceinline__ float relu(float x) { return fmaxf(x, 0.f); }

// ---------------- weight fragment prep ----------------
// B-fragment (m16n8k16 col-major B): lane = g*4+t (g=lane>>2, t=lane&3)
//   b0 = {B[2t][n], B[2t+1][n]},  b1 = {B[2t+8][n], B[2t+9][n]},  n = nt*8+g
__global__ void prep_kernel(const float* __restrict__ W1, const float* __restrict__ W2,
                            const float* __restrict__ W3) {
    int i = blockIdx.x * blockDim.x + threadIdx.x;
    int stride = gridDim.x * blockDim.x;
    for (int idx = i; idx < 6 * 8 * 32; idx += stride) {
        int lane = idx & 31, nt = (idx >> 5) & 7, kt = idx >> 8;
        int g = lane >> 2, t = lane & 3;
        int n = nt * 8 + g;
        int k0 = kt * 16 + t * 2;
        float v0 = (k0     < 85) ? W1[(k0    ) * 64 + n] : 0.f;
        float v1 = (k0 + 1 < 85) ? W1[(k0 + 1) * 64 + n] : 0.f;
        float v2 = (k0 + 8 < 85) ? W1[(k0 + 8) * 64 + n] : 0.f;
        float v3 = (k0 + 9 < 85) ? W1[(k0 + 9) * 64 + n] : 0.f;
        gB1[idx] = make_uint2(pkbf(v0, v1), pkbf(v2, v3));
    }
    for (int idx = i; idx < 4 * 4 * 32; idx += stride) {
        int lane = idx & 31, nt = (idx >> 5) & 3, kt = idx >> 7;
        int g = lane >> 2, t = lane & 3;
        int n = nt * 8 + g;
        int k0 = kt * 16 + t * 2;
        gB2[idx] = make_uint2(pkbf(W2[k0 * 32 + n],       W2[(k0 + 1) * 32 + n]),
                              pkbf(W2[(k0 + 8) * 32 + n], W2[(k0 + 9) * 32 + n]));
    }
    for (int idx = i; idx < 2 * 2 * 32; idx += stride) {
        int lane = idx & 31, nt = (idx >> 5) & 1, kt = idx >> 6;
        int g = lane >> 2, t = lane & 3;
        int n = nt * 8 + g;
        int k0 = kt * 16 + t * 2;
        gB3[idx] = make_uint2(pkbf(W3[k0 * 16 + n],       W3[(k0 + 1) * 16 + n]),
                              pkbf(W3[(k0 + 8) * 16 + n], W3[(k0 + 9) * 16 + n]));
    }
}

// ---------------- main kernel ----------------
__global__ void __launch_bounds__(THREADS)
wd_mma(const int* __restrict__ uids, const int* __restrict__ mids,
       const float* __restrict__ gender, const float* __restrict__ age,
       const float* __restrict__ occ, const float* __restrict__ genres,
       const float* __restrict__ wideW, const float* __restrict__ wideB,
       const float* __restrict__ utab, const float* __restrict__ mtab,
       const float* __restrict__ b1, const float* __restrict__ b2,
       const float* __restrict__ b3, const float* __restrict__ W4,
       const float* __restrict__ b4, float* __restrict__ out)
{
    extern __shared__ __align__(16) char smem[];
    u32*   sA1w  = (u32*)(smem + OFF_A1);
    uint2* sB1f  = (uint2*)(smem + OFF_B1F);
    uint2* sB2f  = (uint2*)(smem + OFF_B2F);
    float* sG    = (float*)(smem + OFF_G);
    int*   sIds  = (int*)(smem + OFF_IDS);
    float* sWide = (float*)(smem + OFF_WIDE);
    float* sB1b  = (float*)(smem + OFF_B1B);
    float* sB2b  = (float*)(smem + OFF_B2B);
    float* sWr   = (float*)(smem + OFF_WR);
    float* sSc   = (float*)(smem + OFF_SC);

    const int tid  = threadIdx.x;
    const int wid  = tid >> 5;
    const int lane = tid & 31;
    const int g    = lane >> 2;
    const int t4   = lane & 3;

    // ---- one-time staging ----
    for (int i = tid; i < 6 * 8 * 32; i += THREADS) sB1f[i] = gB1[i];
    for (int i = tid; i < 4 * 4 * 32; i += THREADS) sB2f[i] = gB2[i];
    if (tid < 64) sB1b[tid] = b1[tid];
    if (tid < 32) sB2b[tid] = b2[tid];
    if (tid < 21) sWr[tid]  = wideW[NU + NM + tid];
    if (tid == 0) { sSc[0] = b4[0]; sSc[1] = wideB[0]; }

    // register-resident layer-3 fragments + per-lane tail constants
    uint2 rB3[2][2];
    #pragma unroll
    for (int kt = 0; kt < 2; kt++)
        #pragma unroll
        for (int nt = 0; nt < 2; nt++)
            rB3[kt][nt] = gB3[(kt * 2 + nt) * 32 + lane];
    const int c0 = 2 * t4;
    float b3c0 = b3[c0],     b3c1 = b3[c0 + 1],     b3c2 = b3[8 + c0],     b3c3 = b3[9 + c0];
    float w4c0 = W4[c0],     w4c1 = W4[c0 + 1],     w4c2 = W4[8 + c0],     w4c3 = W4[9 + c0];
    __syncthreads();

    u32*   myA   = sA1w + wid * (16 * AW);
    float* myG   = sG + wid * 288;
    int*   myIds = sIds + wid * 32;
    float* myWide = sWide + wid * 16;

    for (int tile = blockIdx.x; tile < NTILES; tile += gridDim.x) {
        const int R = tile * 128 + wid * 16;
        __syncwarp();   // prior iteration's reads of myA/myG/myIds done

        // ---- genres: fully coalesced 288-word stream -> smem ----
        {
            const float* gbase = genres + (size_t)R * 18;
            #pragma unroll
            for (int j = 0; j < 9; j++)
                myG[lane + 32 * j] = gbase[lane + 32 * j];
        }
        // ---- ids ----
        if (lane < 16) {
            myIds[lane]      = uids[R + lane];
            myIds[16 + lane] = mids[R + lane];
        }
        __syncwarp();

        // ---- coalesced embedding gather: 8 lanes cover one 128B table row ----
        {
            const int ch = lane & 7;     // 16B chunk
            const int r4 = lane >> 3;    // 0..3
            #pragma unroll
            for (int p = 0; p < 4; p++) {
                const int row = r4 + p * 4;
                const float4 xu = ((const float4*)(utab + (size_t)myIds[row] * 32))[ch];
                const float4 xm = ((const float4*)(mtab + (size_t)myIds[16 + row] * 32))[ch];
                u32* rb = myA + row * AW;
                *(uint2*)(rb + 2 * ch)      = make_uint2(pkbf(xu.x, xu.y), pkbf(xu.z, xu.w));
                *(uint2*)(rb + 16 + 2 * ch) = make_uint2(pkbf(xm.x, xm.y), pkbf(xm.z, xm.w));
            }
        }

        // ---- rest features + wide path (lanes 0..15, one row each) ----
        if (lane < 16) {
            const int r = R + lane;
            float fv[21];
            fv[0] = gender[r]; fv[1] = age[r]; fv[2] = occ[r];
            #pragma unroll
            for (int q = 0; q < 9; q++) {
                float2 p = *(const float2*)(myG + lane * 18 + 2 * q);
                fv[3 + 2 * q] = p.x; fv[4 + 2 * q] = p.y;
            }
            float wide = sSc[1] + wideW[myIds[lane]] + wideW[NU + myIds[16 + lane]];
            #pragma unroll
            for (int i = 0; i < 21; i++) wide = fmaf(fv[i], sWr[i], wide);
            myWide[lane] = wide;

            u32 w[16];
            #pragma unroll
            for (int j = 0; j < 10; j++) w[j] = pkbf(fv[2 * j], fv[2 * j + 1]);
            w[10] = pkbf(fv[20], 0.f);
            w[11] = w[12] = w[13] = w[14] = w[15] = 0u;
            u32* rb = myA + lane * AW + 32;
            #pragma unroll
            for (int j = 0; j < 4; j++)
                *(uint4*)(rb + j * 4) = make_uint4(w[4*j], w[4*j+1], w[4*j+2], w[4*j+3]);
        }
        __syncwarp();

        // ---- layer 1: [16x64] = A1[16x96] * W1 ----
        float acc[8][4];
        #pragma unroll
        for (int nt = 0; nt < 8; nt++)
            acc[nt][0] = acc[nt][1] = acc[nt][2] = acc[nt][3] = 0.f;
        #pragma unroll
        for (int kt = 0; kt < 6; kt++) {
            u32 a0 = myA[g * AW + kt * 8 + t4];
            u32 a1 = myA[(g + 8) * AW + kt * 8 + t4];
            u32 a2 = myA[g * AW + kt * 8 + t4 + 4];
            u32 a3 = myA[(g + 8) * AW + kt * 8 + t4 + 4];
            #pragma unroll
            for (int nt = 0; nt < 8; nt++) {
                uint2 b = sB1f[(kt * 8 + nt) * 32 + lane];
                mma16816(acc[nt], a0, a1, a2, a3, b.x, b.y);
            }
        }

        // ---- epilogue 1: bias+relu, C-frag -> A-frag (registers only) ----
        u32 a2f[4][4];
        #pragma unroll
        for (int kt = 0; kt < 4; kt++) {
            int j0 = 2 * kt, j1 = j0 + 1;
            float2 bb0 = *(const float2*)(sB1b + j0 * 8 + t4 * 2);
            float2 bb1 = *(const float2*)(sB1b + j1 * 8 + t4 * 2);
            a2f[kt][0] = pkbf(relu(acc[j0][0] + bb0.x), relu(acc[j0][1] + bb0.y));
            a2f[kt][1] = pkbf(relu(acc[j0][2] + bb0.x), relu(acc[j0][3] + bb0.y));
            a2f[kt][2] = pkbf(relu(acc[j1][0] + bb1.x), relu(acc[j1][1] + bb1.y));
            a2f[kt][3] = pkbf(relu(acc[j1][2] + bb1.x), relu(acc[j1][3] + bb1.y));
        }

        // ---- layer 2: [16x32] = H1[16x64] * W2 ----
        float acc2[4][4];
        #pragma unroll
        for (int nt = 0; nt < 4; nt++)
            acc2[nt][0] = acc2[nt][1] = acc2[nt][2] = acc2[nt][3] = 0.f;
        #pragma unroll
        for (int kt = 0; kt < 4; kt++)
            #pragma unroll
            for (int nt = 0; nt < 4; nt++) {
                uint2 b = sB2f[(kt * 4 + nt) * 32 + lane];
                mma16816(acc2[nt], a2f[kt][0], a2f[kt][1], a2f[kt][2], a2f[kt][3], b.x, b.y);
            }

        // ---- epilogue 2: bias+relu -> A-frags for layer 3 ----
        u32 a3f[2][4];
        #pragma unroll
        for (int kt = 0; kt < 2; kt++) {
            int j0 = 2 * kt, j1 = j0 + 1;
            float2 bb0 = *(const float2*)(sB2b + j0 * 8 + t4 * 2);
            float2 bb1 = *(const float2*)(sB2b + j1 * 8 + t4 * 2);
            a3f[kt][0] = pkbf(relu(acc2[j0][0] + bb0.x), relu(acc2[j0][1] + bb0.y));
            a3f[kt][1] = pkbf(relu(acc2[j0][2] + bb0.x), relu(acc2[j0][3] + bb0.y));
            a3f[kt][2] = pkbf(relu(acc2[j1][0] + bb1.x), relu(acc2[j1][1] + bb1.y));
            a3f[kt][3] = pkbf(relu(acc2[j1][2] + bb1.x), relu(acc2[j1][3] + bb1.y));
        }

        // ---- layer 3: [16x16] = H2[16x32] * W3 (B-frags in registers) ----
        float acc3[2][4];
        #pragma unroll
        for (int nt = 0; nt < 2; nt++)
            acc3[nt][0] = acc3[nt][1] = acc3[nt][2] = acc3[nt][3] = 0.f;
        #pragma unroll
        for (int kt = 0; kt < 2; kt++)
            #pragma unroll
            for (int nt = 0; nt < 2; nt++)
                mma16816(acc3[nt], a3f[kt][0], a3f[kt][1], a3f[kt][2], a3f[kt][3],
                         rB3[kt][nt].x, rB3[kt][nt].y);

        // ---- layer 4 + sigmoid: per-lane partial dot, quad reduce ----
        float dpg, dph;
        dpg  = relu(acc3[0][0] + b3c0) * w4c0;
        dpg  = fmaf(relu(acc3[0][1] + b3c1), w4c1, dpg);
        dpg  = fmaf(relu(acc3[1][0] + b3c2), w4c2, dpg);
        dpg  = fmaf(relu(acc3[1][1] + b3c3), w4c3, dpg);
        dph  = relu(acc3[0][2] + b3c0) * w4c0;
        dph  = fmaf(relu(acc3[0][3] + b3c1), w4c1, dph);
        dph  = fmaf(relu(acc3[1][2] + b3c2), w4c2, dph);
        dph  = fmaf(relu(acc3[1][3] + b3c3), w4c3, dph);
        dpg += __shfl_xor_sync(0xffffffffu, dpg, 1);
        dpg += __shfl_xor_sync(0xffffffffu, dpg, 2);
        dph += __shfl_xor_sync(0xffffffffu, dph, 1);
        dph += __shfl_xor_sync(0xffffffffu, dph, 2);

        if (t4 == 0) {
            float zg = myWide[g]     + dpg + sSc[0];
            float zh = myWide[g + 8] + dph + sSc[0];
            out[R + g]     = 1.f / (1.f + expf(-zg));
            out[R + g + 8] = 1.f / (1.f + expf(-zh));
        }
    }
}

extern "C" void kernel_launch(void* const* d_in, const int* in_sizes, int n_in,
                              void* d_out, int out_size) {
    const int*   uids   = (const int*)  d_in[0];
    const int*   mids   = (const int*)  d_in[1];
    const float* gender = (const float*)d_in[2];
    const float* age    = (const float*)d_in[3];
    const float* occ    = (const float*)d_in[4];
    const float* genres = (const float*)d_in[5];
    const float* wideW  = (const float*)d_in[6];
    const float* wideB  = (const float*)d_in[7];
    const float* utab   = (const float*)d_in[8];
    const float* mtab   = (const float*)d_in[9];
    const float* W1     = (const float*)d_in[10];
    const float* b1     = (const float*)d_in[11];
    const float* W2     = (const float*)d_in[12];
    const float* b2     = (const float*)d_in[13];
    const float* W3     = (const float*)d_in[14];
    const float* b3     = (const float*)d_in[15];
    const float* W4     = (const float*)d_in[16];
    const float* b4     = (const float*)d_in[17];
    float* out = (float*)d_out;

    static int inited = 0;
    if (!inited) {
        cudaFuncSetAttribute(wd_mma, cudaFuncAttributeMaxDynamicSharedMemorySize, SMEM_BYTES);
        inited = 1;
    }

    prep_kernel<<<4, 256>>>(W1, W2, W3);
    wd_mma<<<GRID, THREADS, SMEM_BYTES>>>(uids, mids, gender, age, occ, genres,
                                          wideW, wideB, utab, mtab,
                                          b1, b2, b3, W4, b4, out);
}